// round 3
// baseline (speedup 1.0000x reference)
#include <cuda_runtime.h>
#include <cuda_bf16.h>
#include <cstdint>

// ----------------------------------------------------------------------------
// Problem constants
// ----------------------------------------------------------------------------
#define NROWS 8192   // x rows (output rows)
#define MROWS 8192   // y rows (output cols)
#define DDIM  512
#define GAMMA 0.002f

// Tile geometry: CTA computes TM x TN outputs.
#define TM 128
#define TN 256

// tcgen05 is arch-specific (sm_103a). The harness build includes a family
// (plain sm_103) PTX pass where tcgen05 is illegal, so gate on the
// arch-specific feature macros and provide a SIMT fallback for other passes.
#if !defined(__CUDA_ARCH__)
#  define USE_TCGEN05 1
#elif defined(__CUDA_ARCH_FEAT_SM103_ALL) || defined(__CUDA_ARCH_FEAT_SM100_ALL)
#  define USE_TCGEN05 1
#elif defined(__CUDA_ARCH_SPECIFIC__)
#  define USE_TCGEN05 1
#else
#  define USE_TCGEN05 0
#endif

// ----------------------------------------------------------------------------
// Scratch (device globals — no allocation allowed)
// ----------------------------------------------------------------------------
__device__ __nv_bfloat16 g_xhi[NROWS * DDIM];
__device__ __nv_bfloat16 g_xlo[NROWS * DDIM];
__device__ __nv_bfloat16 g_yhi[MROWS * DDIM];
__device__ __nv_bfloat16 g_ylo[MROWS * DDIM];
__device__ float         g_xsq[NROWS];
__device__ float         g_ysq[MROWS];

// ----------------------------------------------------------------------------
// Prep: fp32 -> bf16 hi/lo split + row |v|^2   (arch-portable)
// ----------------------------------------------------------------------------
__global__ void __launch_bounds__(256) prep_kernel(const float* __restrict__ in, int which) {
    __nv_bfloat16* hi = which ? g_yhi : g_xhi;
    __nv_bfloat16* lo = which ? g_ylo : g_xlo;
    float* sq         = which ? g_ysq : g_xsq;

    const int warp = threadIdx.x >> 5;
    const int lane = threadIdx.x & 31;
    const int row  = blockIdx.x * 8 + warp;
    const float* src = in + (size_t)row * DDIM;

    float s = 0.f;
    #pragma unroll
    for (int it = 0; it < 4; ++it) {
        const int col = it * 128 + lane * 4;
        const float4 v = *reinterpret_cast<const float4*>(src + col);
        s += v.x * v.x + v.y * v.y + v.z * v.z + v.w * v.w;

        __nv_bfloat16 h0 = __float2bfloat16(v.x);
        __nv_bfloat16 h1 = __float2bfloat16(v.y);
        __nv_bfloat16 h2 = __float2bfloat16(v.z);
        __nv_bfloat16 h3 = __float2bfloat16(v.w);
        __nv_bfloat16 l0 = __float2bfloat16(v.x - __bfloat162float(h0));
        __nv_bfloat16 l1 = __float2bfloat16(v.y - __bfloat162float(h1));
        __nv_bfloat16 l2 = __float2bfloat16(v.z - __bfloat162float(h2));
        __nv_bfloat16 l3 = __float2bfloat16(v.w - __bfloat162float(h3));

        __nv_bfloat162 hp0 = __halves2bfloat162(h0, h1);
        __nv_bfloat162 hp1 = __halves2bfloat162(h2, h3);
        __nv_bfloat162 lp0 = __halves2bfloat162(l0, l1);
        __nv_bfloat162 lp1 = __halves2bfloat162(l2, l3);

        uint2 hv = make_uint2(*reinterpret_cast<uint32_t*>(&hp0),
                              *reinterpret_cast<uint32_t*>(&hp1));
        uint2 lv = make_uint2(*reinterpret_cast<uint32_t*>(&lp0),
                              *reinterpret_cast<uint32_t*>(&lp1));
        *reinterpret_cast<uint2*>(hi + (size_t)row * DDIM + col) = hv;
        *reinterpret_cast<uint2*>(lo + (size_t)row * DDIM + col) = lv;
    }
    #pragma unroll
    for (int o = 16; o; o >>= 1) s += __shfl_xor_sync(0xffffffff, s, o);
    if (lane == 0) sq[row] = s;
}

// ----------------------------------------------------------------------------
// SMEM layout (shared by both variants for a single launch geometry)
//   header 1024B: [0] tmem ptr, [8] mbar0, [16] mbar1
//   2 stages x (Ahi 16K | Alo 16K | Bhi 32K | Blo 32K) = 2 x 96K
// ----------------------------------------------------------------------------
#define A_TILE_BYTES  (TM * 128)              // 16384
#define B_TILE_BYTES  (TN * 128)              // 32768
#define STAGE_BYTES   (2 * A_TILE_BYTES + 2 * B_TILE_BYTES)  // 98304
#define SMEM_MBAR0    8
#define SMEM_MBAR1    16
#define SMEM_TILES    1024
#define SMEM_TOTAL    (SMEM_TILES + 2 * STAGE_BYTES)         // 197632

#if USE_TCGEN05
// ============================================================================
// tcgen05 implementation (sm_103a passes only)
// ============================================================================
__device__ __forceinline__ uint32_t smem_u32(const void* p) {
    uint32_t a;
    asm("{ .reg .u64 t; cvta.to.shared.u64 t, %1; cvt.u32.u64 %0, t; }" : "=r"(a) : "l"(p));
    return a;
}

__device__ __forceinline__ uint32_t elect_one() {
    uint32_t pred;
    asm volatile("{\n\t.reg .pred p;\n\telect.sync _|p, 0xFFFFFFFF;\n\tselp.b32 %0, 1, 0, p;\n\t}"
                 : "=r"(pred));
    return pred;
}

#define TCGEN05_ALLOC(smem_addr, ncols) \
    asm volatile("tcgen05.alloc.cta_group::1.sync.aligned.shared::cta.b32 [%0], %1;" \
                 :: "r"((uint32_t)(smem_addr)), "r"((uint32_t)(ncols)) : "memory")
#define TCGEN05_DEALLOC(tmem, ncols) \
    asm volatile("tcgen05.dealloc.cta_group::1.sync.aligned.b32 %0, %1;" \
                 :: "r"(tmem), "r"((uint32_t)(ncols)))
#define TCGEN05_RELINQ() \
    asm volatile("tcgen05.relinquish_alloc_permit.cta_group::1.sync.aligned;")
#define TCGEN05_COMMIT(mbar) \
    asm volatile("tcgen05.commit.cta_group::1.mbarrier::arrive::one.shared::cluster.b64 [%0];" \
                 :: "r"((uint32_t)(mbar)) : "memory")
#define TCGEN05_WAIT_LD() asm volatile("tcgen05.wait::ld.sync.aligned;" ::: "memory")
#define TCGEN05_FENCE_AFTER()  asm volatile("tcgen05.fence::after_thread_sync;" ::: "memory")
#define TCGEN05_FENCE_BEFORE() asm volatile("tcgen05.fence::before_thread_sync;" ::: "memory")
#define FENCE_PROXY_ASYNC() asm volatile("fence.proxy.async.shared::cta;" ::: "memory")

#define MBARRIER_INIT(mbar, cnt) \
    asm volatile("mbarrier.init.shared.b64 [%0], %1;" \
                 :: "r"((uint32_t)(mbar)), "r"((uint32_t)(cnt)) : "memory")
#define MBARRIER_INVAL(mbar) \
    asm volatile("mbarrier.inval.shared.b64 [%0];" :: "r"((uint32_t)(mbar)) : "memory")

#define MBARRIER_WAIT_PARITY(mbar, parity) do {                                         \
    uint32_t _m = (uint32_t)(mbar);                                                     \
    uint32_t _p = (uint32_t)(parity);                                                   \
    uint32_t _done;                                                                     \
    asm volatile("{\n\t.reg .pred p;\n\t"                                               \
                 "mbarrier.try_wait.parity.acquire.cta.shared::cta.b64 p, [%1], %2;\n\t"\
                 "selp.b32 %0, 1, 0, p;\n\t}"                                           \
                 : "=r"(_done) : "r"(_m), "r"(_p) : "memory");                          \
    if (!_done) {                                                                       \
        asm volatile("{\n\t.reg .pred P1;\n\t"                                          \
            "WAIT_LOOP_%=:\n\t"                                                         \
            "mbarrier.try_wait.parity.acquire.cta.shared::cta.b64 P1, [%0], %1, 0x989680;\n\t" \
            "@P1 bra.uni WAIT_DONE_%=;\n\t"                                             \
            "bra.uni WAIT_LOOP_%=;\n\t"                                                 \
            "WAIT_DONE_%=:\n\t}"                                                        \
            :: "r"(_m), "r"(_p) : "memory");                                            \
    }                                                                                   \
} while (0)

#define TCGEN05_LD_32X32B_X32(r, tmem_addr) \
    asm volatile( \
        "tcgen05.ld.sync.aligned.32x32b.x32.b32 " \
        "{%0, %1, %2, %3, %4, %5, %6, %7, " \
        " %8, %9, %10, %11, %12, %13, %14, %15, " \
        " %16, %17, %18, %19, %20, %21, %22, %23, " \
        " %24, %25, %26, %27, %28, %29, %30, %31}, [%32];" \
        : "=r"((r)[0]),  "=r"((r)[1]),  "=r"((r)[2]),  "=r"((r)[3]), \
          "=r"((r)[4]),  "=r"((r)[5]),  "=r"((r)[6]),  "=r"((r)[7]), \
          "=r"((r)[8]),  "=r"((r)[9]),  "=r"((r)[10]), "=r"((r)[11]), \
          "=r"((r)[12]), "=r"((r)[13]), "=r"((r)[14]), "=r"((r)[15]), \
          "=r"((r)[16]), "=r"((r)[17]), "=r"((r)[18]), "=r"((r)[19]), \
          "=r"((r)[20]), "=r"((r)[21]), "=r"((r)[22]), "=r"((r)[23]), \
          "=r"((r)[24]), "=r"((r)[25]), "=r"((r)[26]), "=r"((r)[27]), \
          "=r"((r)[28]), "=r"((r)[29]), "=r"((r)[30]), "=r"((r)[31]) \
        : "r"(tmem_addr))

#define CP_ASYNC16(dst, src) \
    asm volatile("cp.async.cg.shared.global [%0], [%1], 16;" \
                 :: "r"((uint32_t)(dst)), "l"(src) : "memory")
#define CP_ASYNC_COMMIT() asm volatile("cp.async.commit_group;" ::: "memory")
#define CP_ASYNC_WAIT0()  asm volatile("cp.async.wait_group 0;" ::: "memory")

__device__ __forceinline__ void mma_bf16_ss(uint32_t d_tmem, uint64_t a_desc,
                                            uint64_t b_desc, uint32_t idesc,
                                            uint32_t enable) {
    asm volatile(
        "{\n\t.reg .pred p;\n\tsetp.ne.u32 p, %4, 0;\n\t"
        "tcgen05.mma.cta_group::1.kind::f16 [%0], %1, %2, %3, {%5, %5, %5, %5}, p;\n\t}"
        :: "r"(d_tmem), "l"(a_desc), "l"(b_desc), "r"(idesc), "r"(enable), "r"(0u)
        : "memory");
}

// SMEM descriptor: SW128, version=1(Blackwell), SBO=64, LBO=1 (K-major 128B rows)
static __device__ __forceinline__ uint64_t make_desc(uint32_t smem_addr) {
    constexpr uint64_t BASE =
        (uint64_t(2) << 61) | (uint64_t(1) << 46) | (uint64_t(64) << 32) | (uint64_t(1) << 16);
    return BASE | ((uint64_t)(smem_addr >> 4) & 0x3FFF);
}

// idesc: dtype=F32(bit4), atype=BF16(bit7), btype=BF16(bit10), N/8<<17, M/16<<24
#define MMA_IDESC ((1u << 4) | (1u << 7) | (1u << 10) | (((unsigned)TN / 8) << 17) | (((unsigned)TM / 16) << 24))

// cp.async one tile: ROWS x 64 bf16 (128B SW128 rows) from gmem row-major.
template <int ROWS>
__device__ __forceinline__ void load_tile_ca(const __nv_bfloat16* __restrict__ gbase,
                                             uint32_t sdst, int tid) {
    #pragma unroll
    for (int it = 0; it < ROWS / 16; ++it) {      // ROWS*8 / 128 threads
        const int idx = it * 128 + tid;
        const int r   = idx >> 3;
        const int seg = idx & 7;
        uint32_t off = (uint32_t)(r * 128 + seg * 16);
        off ^= (off >> 3) & 0x70;                  // SW128 swizzle
        CP_ASYNC16(sdst + off, gbase + (size_t)r * DDIM + seg * 8);
    }
}

__device__ __forceinline__ void load_chunk(int rowA, int rowB, int c, uint32_t sb,
                                           int stage, int tid) {
    const size_t koff = (size_t)c * 64;
    const uint32_t s0 = sb + SMEM_TILES + stage * STAGE_BYTES;
    load_tile_ca<TM>(g_xhi + (size_t)rowA * DDIM + koff, s0, tid);
    load_tile_ca<TM>(g_xlo + (size_t)rowA * DDIM + koff, s0 + A_TILE_BYTES, tid);
    load_tile_ca<TN>(g_yhi + (size_t)rowB * DDIM + koff, s0 + 2 * A_TILE_BYTES, tid);
    load_tile_ca<TN>(g_ylo + (size_t)rowB * DDIM + koff, s0 + 2 * A_TILE_BYTES + B_TILE_BYTES, tid);
    CP_ASYNC_COMMIT();
}

__global__ void __launch_bounds__(128) rbf_gemm_kernel(const float* __restrict__ x,
                                                       const float* __restrict__ y,
                                                       float* __restrict__ out) {
    extern __shared__ __align__(1024) char smem[];
    const uint32_t sb  = smem_u32(smem);
    const int tid = threadIdx.x;
    const int wid = tid >> 5;
    const int lid = tid & 31;

    if (wid == 0) {
        TCGEN05_ALLOC(sb, 256);
        TCGEN05_RELINQ();
    }
    __syncthreads();
    uint32_t tmem;
    asm volatile("ld.shared.b32 %0, [%1];" : "=r"(tmem) : "r"(sb));

    if (tid == 0) {
        MBARRIER_INIT(sb + SMEM_MBAR0, 1);
        MBARRIER_INIT(sb + SMEM_MBAR1, 1);
    }
    __syncthreads();

    const int rowA = blockIdx.y * TM;
    const int rowB = blockIdx.x * TN;

    // Prologue: loads for chunk 0 into stage 0.
    load_chunk(rowA, rowB, 0, sb, 0, tid);

    int ph[2] = {0, 0};   // per-stage mma-completion parity counters

    for (int c = 0; c < 8; ++c) {
        const int s = c & 1;
        const uint32_t stageBase = sb + SMEM_TILES + s * STAGE_BYTES;

        // Wait for this chunk's cp.async group (only group outstanding).
        CP_ASYNC_WAIT0();
        FENCE_PROXY_ASYNC();
        __syncthreads();

        // Issue MMAs for chunk c (async; completion tracked on mbar[s]).
        if (wid == 0 && elect_one()) {
            const uint64_t dAh = make_desc(stageBase);
            const uint64_t dAl = make_desc(stageBase + A_TILE_BYTES);
            const uint64_t dBh = make_desc(stageBase + 2 * A_TILE_BYTES);
            const uint64_t dBl = make_desc(stageBase + 2 * A_TILE_BYTES + B_TILE_BYTES);
            #pragma unroll
            for (int k = 0; k < 4; ++k) {
                const uint32_t en0 = (c == 0 && k == 0) ? 0u : 1u;
                mma_bf16_ss(tmem, dAh + k * 2, dBh + k * 2, MMA_IDESC, en0);
                mma_bf16_ss(tmem, dAh + k * 2, dBl + k * 2, MMA_IDESC, 1u);
                mma_bf16_ss(tmem, dAl + k * 2, dBh + k * 2, MMA_IDESC, 1u);
            }
            TCGEN05_COMMIT(sb + (s ? SMEM_MBAR1 : SMEM_MBAR0));
        }

        // Load chunk c+1 into the other stage (wait for MMA c-1 to release it).
        if (c + 1 < 8) {
            const int s2 = (c + 1) & 1;
            if (c >= 1) {
                MBARRIER_WAIT_PARITY(sb + (s2 ? SMEM_MBAR1 : SMEM_MBAR0), ph[s2] & 1);
                ph[s2]++;
            }
            load_chunk(rowA, rowB, c + 1, sb, s2, tid);
        }
    }

    // Wait for the final chunk's MMAs (chunk 7, stage 1). commit covers all
    // previously issued tcgen05.mma from this thread, so this implies all done.
    MBARRIER_WAIT_PARITY(sb + SMEM_MBAR1, ph[1] & 1);
    TCGEN05_FENCE_AFTER();

    // Epilogue: each warp owns its 32-row TMEM subpartition; TN=256 cols.
    const int m = rowA + wid * 32 + lid;
    const float xs = g_xsq[m];
    float* orow = out + (size_t)m * MROWS + rowB;

    #pragma unroll
    for (int nb = 0; nb < TN / 32; ++nb) {
        uint32_t r[32];
        TCGEN05_LD_32X32B_X32(r, tmem + nb * 32);
        TCGEN05_WAIT_LD();
        #pragma unroll
        for (int j = 0; j < 32; j += 4) {
            float4 o;
            float d0 = xs + g_ysq[rowB + nb * 32 + j + 0] - 2.f * __uint_as_float(r[j + 0]);
            float d1 = xs + g_ysq[rowB + nb * 32 + j + 1] - 2.f * __uint_as_float(r[j + 1]);
            float d2 = xs + g_ysq[rowB + nb * 32 + j + 2] - 2.f * __uint_as_float(r[j + 2]);
            float d3 = xs + g_ysq[rowB + nb * 32 + j + 3] - 2.f * __uint_as_float(r[j + 3]);
            o.x = __expf(-GAMMA * fmaxf(d0, 0.f));
            o.y = __expf(-GAMMA * fmaxf(d1, 0.f));
            o.z = __expf(-GAMMA * fmaxf(d2, 0.f));
            o.w = __expf(-GAMMA * fmaxf(d3, 0.f));
            *reinterpret_cast<float4*>(orow + nb * 32 + j) = o;
        }
    }
    TCGEN05_FENCE_BEFORE();

    __syncthreads();
    if (tid == 0) {
        MBARRIER_INVAL(sb + SMEM_MBAR0);
        MBARRIER_INVAL(sb + SMEM_MBAR1);
    }
    __syncthreads();
    if (wid == 0) TCGEN05_DEALLOC(tmem, 256);
}

#else  // !USE_TCGEN05
// ============================================================================
// SIMT fp32 fallback (family / non-'a' passes): same launch geometry,
// tile = 128 x 256 handled as two 128x128 halves.
// ============================================================================
__global__ void __launch_bounds__(128) rbf_gemm_kernel(const float* __restrict__ x,
                                                       const float* __restrict__ y,
                                                       float* __restrict__ out) {
    extern __shared__ __align__(1024) char smem[];
    float* As = reinterpret_cast<float*>(smem);            // [16][128]
    float* Bs = As + 16 * 128;                             // [16][128]

    const int tid = threadIdx.x;
    const int tx = tid & 15;
    const int ty = tid >> 4;
    const int rowA = blockIdx.y * TM;

    for (int half = 0; half < 2; ++half) {
        const int rowB = blockIdx.x * TN + half * 128;

        float acc[16][8];
        #pragma unroll
        for (int i = 0; i < 16; ++i)
            #pragma unroll
            for (int j = 0; j < 8; ++j) acc[i][j] = 0.f;

        for (int k0 = 0; k0 < DDIM; k0 += 16) {
            #pragma unroll
            for (int it = 0; it < 16; ++it) {
                const int idx = it * 128 + tid;
                const int r  = idx >> 4;
                const int kk = idx & 15;
                As[kk * 128 + r] = x[(size_t)(rowA + r) * DDIM + k0 + kk];
                Bs[kk * 128 + r] = y[(size_t)(rowB + r) * DDIM + k0 + kk];
            }
            __syncthreads();
            #pragma unroll
            for (int kk = 0; kk < 16; ++kk) {
                float a[16], b[8];
                #pragma unroll
                for (int i = 0; i < 16; ++i) a[i] = As[kk * 128 + ty * 16 + i];
                #pragma unroll
                for (int j = 0; j < 8; ++j)  b[j] = Bs[kk * 128 + tx * 8 + j];
                #pragma unroll
                for (int i = 0; i < 16; ++i)
                    #pragma unroll
                    for (int j = 0; j < 8; ++j) acc[i][j] += a[i] * b[j];
            }
            __syncthreads();
        }

        #pragma unroll
        for (int i = 0; i < 16; ++i) {
            const int m = rowA + ty * 16 + i;
            const float xs = g_xsq[m];
            #pragma unroll
            for (int j = 0; j < 8; ++j) {
                const int cc = rowB + tx * 8 + j;
                float d = xs + g_ysq[cc] - 2.f * acc[i][j];
                out[(size_t)m * MROWS + cc] = __expf(-GAMMA * fmaxf(d, 0.f));
            }
        }
        __syncthreads();
    }
}
#endif // USE_TCGEN05

// ----------------------------------------------------------------------------
// Launch
// ----------------------------------------------------------------------------
extern "C" void kernel_launch(void* const* d_in, const int* in_sizes, int n_in,
                              void* d_out, int out_size) {
    const float* x = (const float*)d_in[0];
    const float* y = (const float*)d_in[1];
    float* out = (float*)d_out;

    prep_kernel<<<NROWS / 8, 256>>>(x, 0);
    prep_kernel<<<MROWS / 8, 256>>>(y, 1);

    cudaFuncSetAttribute(rbf_gemm_kernel, cudaFuncAttributeMaxDynamicSharedMemorySize,
                         SMEM_TOTAL);
    dim3 grid(MROWS / TN, NROWS / TM);
    rbf_gemm_kernel<<<grid, 128, SMEM_TOTAL>>>(x, y, out);
}

// round 4
// speedup vs baseline: 2.0869x; 2.0869x over previous
#include <cuda_runtime.h>
#include <cuda_fp16.h>
#include <cstdint>

// ----------------------------------------------------------------------------
// Problem constants
// ----------------------------------------------------------------------------
#define NROWS 8192   // x rows (output rows)
#define MROWS 8192   // y rows (output cols)
#define DDIM  512
#define GAMMA 0.002f

// Tile geometry: CTA computes TM x TN outputs.
#define TM 128
#define TN 256

// tcgen05 is arch-specific (sm_103a). The harness build includes a family
// (plain sm_103) PTX pass where tcgen05 is illegal, so gate on the
// arch-specific feature macros and provide a SIMT fallback for other passes.
#if !defined(__CUDA_ARCH__)
#  define USE_TCGEN05 1
#elif defined(__CUDA_ARCH_FEAT_SM103_ALL) || defined(__CUDA_ARCH_FEAT_SM100_ALL)
#  define USE_TCGEN05 1
#elif defined(__CUDA_ARCH_SPECIFIC__)
#  define USE_TCGEN05 1
#else
#  define USE_TCGEN05 0
#endif

// ----------------------------------------------------------------------------
// Scratch (device globals — no allocation allowed)
// ----------------------------------------------------------------------------
__device__ __half g_xh[NROWS * DDIM];
__device__ __half g_yh[MROWS * DDIM];
__device__ float  g_xsq[NROWS];
__device__ float  g_ysq[MROWS];

// ----------------------------------------------------------------------------
// Prep: fp32 -> fp16 + row |v|^2 (fp32 exact)   (arch-portable)
// ----------------------------------------------------------------------------
__global__ void __launch_bounds__(256) prep_kernel(const float* __restrict__ in, int which) {
    __half* h  = which ? g_yh : g_xh;
    float* sq  = which ? g_ysq : g_xsq;

    const int warp = threadIdx.x >> 5;
    const int lane = threadIdx.x & 31;
    const int row  = blockIdx.x * 8 + warp;
    const float* src = in + (size_t)row * DDIM;

    float s = 0.f;
    #pragma unroll
    for (int it = 0; it < 4; ++it) {
        const int col = it * 128 + lane * 4;
        const float4 v = *reinterpret_cast<const float4*>(src + col);
        s += v.x * v.x + v.y * v.y + v.z * v.z + v.w * v.w;

        __half2 p0 = __floats2half2_rn(v.x, v.y);
        __half2 p1 = __floats2half2_rn(v.z, v.w);
        uint2 hv = make_uint2(*reinterpret_cast<uint32_t*>(&p0),
                              *reinterpret_cast<uint32_t*>(&p1));
        *reinterpret_cast<uint2*>(h + (size_t)row * DDIM + col) = hv;
    }
    #pragma unroll
    for (int o = 16; o; o >>= 1) s += __shfl_xor_sync(0xffffffff, s, o);
    if (lane == 0) sq[row] = s;
}

// ----------------------------------------------------------------------------
// SMEM layout:
//   header 1024B: [0] tmem ptr, [8] mbar0, [16] mbar1
//   2 stages x (A 16K | B 32K) = 2 x 48K   -> total 99328 bytes (2 CTAs/SM)
// ----------------------------------------------------------------------------
#define A_TILE_BYTES  (TM * 128)              // 16384
#define B_TILE_BYTES  (TN * 128)              // 32768
#define STAGE_BYTES   (A_TILE_BYTES + B_TILE_BYTES)          // 49152
#define SMEM_MBAR0    8
#define SMEM_MBAR1    16
#define SMEM_TILES    1024
#define SMEM_TOTAL    (SMEM_TILES + 2 * STAGE_BYTES)         // 99328

#if USE_TCGEN05
// ============================================================================
// tcgen05 implementation (sm_103a passes only)
// ============================================================================
__device__ __forceinline__ uint32_t smem_u32(const void* p) {
    uint32_t a;
    asm("{ .reg .u64 t; cvta.to.shared.u64 t, %1; cvt.u32.u64 %0, t; }" : "=r"(a) : "l"(p));
    return a;
}

__device__ __forceinline__ uint32_t elect_one() {
    uint32_t pred;
    asm volatile("{\n\t.reg .pred p;\n\telect.sync _|p, 0xFFFFFFFF;\n\tselp.b32 %0, 1, 0, p;\n\t}"
                 : "=r"(pred));
    return pred;
}

#define TCGEN05_ALLOC(smem_addr, ncols) \
    asm volatile("tcgen05.alloc.cta_group::1.sync.aligned.shared::cta.b32 [%0], %1;" \
                 :: "r"((uint32_t)(smem_addr)), "r"((uint32_t)(ncols)) : "memory")
#define TCGEN05_DEALLOC(tmem, ncols) \
    asm volatile("tcgen05.dealloc.cta_group::1.sync.aligned.b32 %0, %1;" \
                 :: "r"(tmem), "r"((uint32_t)(ncols)))
#define TCGEN05_RELINQ() \
    asm volatile("tcgen05.relinquish_alloc_permit.cta_group::1.sync.aligned;")
#define TCGEN05_COMMIT(mbar) \
    asm volatile("tcgen05.commit.cta_group::1.mbarrier::arrive::one.shared::cluster.b64 [%0];" \
                 :: "r"((uint32_t)(mbar)) : "memory")
#define TCGEN05_WAIT_LD() asm volatile("tcgen05.wait::ld.sync.aligned;" ::: "memory")
#define TCGEN05_FENCE_AFTER()  asm volatile("tcgen05.fence::after_thread_sync;" ::: "memory")
#define TCGEN05_FENCE_BEFORE() asm volatile("tcgen05.fence::before_thread_sync;" ::: "memory")
#define FENCE_PROXY_ASYNC() asm volatile("fence.proxy.async.shared::cta;" ::: "memory")

#define MBARRIER_INIT(mbar, cnt) \
    asm volatile("mbarrier.init.shared.b64 [%0], %1;" \
                 :: "r"((uint32_t)(mbar)), "r"((uint32_t)(cnt)) : "memory")
#define MBARRIER_INVAL(mbar) \
    asm volatile("mbarrier.inval.shared.b64 [%0];" :: "r"((uint32_t)(mbar)) : "memory")

#define MBARRIER_WAIT_PARITY(mbar, parity) do {                                         \
    uint32_t _m = (uint32_t)(mbar);                                                     \
    uint32_t _p = (uint32_t)(parity);                                                   \
    uint32_t _done;                                                                     \
    asm volatile("{\n\t.reg .pred p;\n\t"                                               \
                 "mbarrier.try_wait.parity.acquire.cta.shared::cta.b64 p, [%1], %2;\n\t"\
                 "selp.b32 %0, 1, 0, p;\n\t}"                                           \
                 : "=r"(_done) : "r"(_m), "r"(_p) : "memory");                          \
    if (!_done) {                                                                       \
        asm volatile("{\n\t.reg .pred P1;\n\t"                                          \
            "WAIT_LOOP_%=:\n\t"                                                         \
            "mbarrier.try_wait.parity.acquire.cta.shared::cta.b64 P1, [%0], %1, 0x989680;\n\t" \
            "@P1 bra.uni WAIT_DONE_%=;\n\t"                                             \
            "bra.uni WAIT_LOOP_%=;\n\t"                                                 \
            "WAIT_DONE_%=:\n\t}"                                                        \
            :: "r"(_m), "r"(_p) : "memory");                                            \
    }                                                                                   \
} while (0)

#define TCGEN05_LD_32X32B_X32(r, tmem_addr) \
    asm volatile( \
        "tcgen05.ld.sync.aligned.32x32b.x32.b32 " \
        "{%0, %1, %2, %3, %4, %5, %6, %7, " \
        " %8, %9, %10, %11, %12, %13, %14, %15, " \
        " %16, %17, %18, %19, %20, %21, %22, %23, " \
        " %24, %25, %26, %27, %28, %29, %30, %31}, [%32];" \
        : "=r"((r)[0]),  "=r"((r)[1]),  "=r"((r)[2]),  "=r"((r)[3]), \
          "=r"((r)[4]),  "=r"((r)[5]),  "=r"((r)[6]),  "=r"((r)[7]), \
          "=r"((r)[8]),  "=r"((r)[9]),  "=r"((r)[10]), "=r"((r)[11]), \
          "=r"((r)[12]), "=r"((r)[13]), "=r"((r)[14]), "=r"((r)[15]), \
          "=r"((r)[16]), "=r"((r)[17]), "=r"((r)[18]), "=r"((r)[19]), \
          "=r"((r)[20]), "=r"((r)[21]), "=r"((r)[22]), "=r"((r)[23]), \
          "=r"((r)[24]), "=r"((r)[25]), "=r"((r)[26]), "=r"((r)[27]), \
          "=r"((r)[28]), "=r"((r)[29]), "=r"((r)[30]), "=r"((r)[31]) \
        : "r"(tmem_addr))

#define CP_ASYNC16(dst, src) \
    asm volatile("cp.async.cg.shared.global [%0], [%1], 16;" \
                 :: "r"((uint32_t)(dst)), "l"(src) : "memory")
#define CP_ASYNC_COMMIT() asm volatile("cp.async.commit_group;" ::: "memory")
#define CP_ASYNC_WAIT0()  asm volatile("cp.async.wait_group 0;" ::: "memory")

__device__ __forceinline__ void mma_f16_ss(uint32_t d_tmem, uint64_t a_desc,
                                           uint64_t b_desc, uint32_t idesc,
                                           uint32_t enable) {
    asm volatile(
        "{\n\t.reg .pred p;\n\tsetp.ne.u32 p, %4, 0;\n\t"
        "tcgen05.mma.cta_group::1.kind::f16 [%0], %1, %2, %3, {%5, %5, %5, %5}, p;\n\t}"
        :: "r"(d_tmem), "l"(a_desc), "l"(b_desc), "r"(idesc), "r"(enable), "r"(0u)
        : "memory");
}

// SMEM descriptor: SW128, version=1(Blackwell), SBO=64, LBO=1 (K-major 128B rows)
static __device__ __forceinline__ uint64_t make_desc(uint32_t smem_addr) {
    constexpr uint64_t BASE =
        (uint64_t(2) << 61) | (uint64_t(1) << 46) | (uint64_t(64) << 32) | (uint64_t(1) << 16);
    return BASE | ((uint64_t)(smem_addr >> 4) & 0x3FFF);
}

// idesc for kind::f16, fp16 inputs (atype=btype=0), fp32 accum (dtype=1):
#define MMA_IDESC ((1u << 4) | (((unsigned)TN / 8) << 17) | (((unsigned)TM / 16) << 24))

// cp.async one tile: ROWS x 64 fp16 (128B SW128 rows) from gmem row-major.
template <int ROWS>
__device__ __forceinline__ void load_tile_ca(const __half* __restrict__ gbase,
                                             uint32_t sdst, int tid) {
    #pragma unroll
    for (int it = 0; it < ROWS / 16; ++it) {      // ROWS*8 / 128 threads
        const int idx = it * 128 + tid;
        const int r   = idx >> 3;
        const int seg = idx & 7;
        uint32_t off = (uint32_t)(r * 128 + seg * 16);
        off ^= (off >> 3) & 0x70;                  // SW128 swizzle
        CP_ASYNC16(sdst + off, gbase + (size_t)r * DDIM + seg * 8);
    }
}

__device__ __forceinline__ void load_chunk(int rowA, int rowB, int c, uint32_t sb,
                                           int stage, int tid) {
    const size_t koff = (size_t)c * 64;
    const uint32_t s0 = sb + SMEM_TILES + stage * STAGE_BYTES;
    load_tile_ca<TM>(g_xh + (size_t)rowA * DDIM + koff, s0, tid);
    load_tile_ca<TN>(g_yh + (size_t)rowB * DDIM + koff, s0 + A_TILE_BYTES, tid);
    CP_ASYNC_COMMIT();
}

__global__ void __launch_bounds__(128, 2) rbf_gemm_kernel(const float* __restrict__ x,
                                                          const float* __restrict__ y,
                                                          float* __restrict__ out) {
    extern __shared__ __align__(1024) char smem[];
    const uint32_t sb  = smem_u32(smem);
    const int tid = threadIdx.x;
    const int wid = tid >> 5;
    const int lid = tid & 31;

    if (wid == 0) {
        TCGEN05_ALLOC(sb, 256);
        TCGEN05_RELINQ();
    }
    __syncthreads();
    uint32_t tmem;
    asm volatile("ld.shared.b32 %0, [%1];" : "=r"(tmem) : "r"(sb));

    if (tid == 0) {
        MBARRIER_INIT(sb + SMEM_MBAR0, 1);
        MBARRIER_INIT(sb + SMEM_MBAR1, 1);
    }
    __syncthreads();

    const int rowA = blockIdx.y * TM;
    const int rowB = blockIdx.x * TN;

    // Prologue: loads for chunk 0 into stage 0.
    load_chunk(rowA, rowB, 0, sb, 0, tid);

    int ph[2] = {0, 0};   // per-stage mma-completion parity counters

    for (int c = 0; c < 8; ++c) {
        const int s = c & 1;
        const uint32_t stageBase = sb + SMEM_TILES + s * STAGE_BYTES;

        // Wait for this chunk's cp.async group (only group outstanding).
        CP_ASYNC_WAIT0();
        FENCE_PROXY_ASYNC();
        __syncthreads();

        // Issue MMAs for chunk c (async; completion tracked on mbar[s]).
        if (wid == 0 && elect_one()) {
            const uint64_t dA = make_desc(stageBase);
            const uint64_t dB = make_desc(stageBase + A_TILE_BYTES);
            #pragma unroll
            for (int k = 0; k < 4; ++k) {          // 4 x K=16 per 64-chunk
                const uint32_t en0 = (c == 0 && k == 0) ? 0u : 1u;
                mma_f16_ss(tmem, dA + k * 2, dB + k * 2, MMA_IDESC, en0);
            }
            TCGEN05_COMMIT(sb + (s ? SMEM_MBAR1 : SMEM_MBAR0));
        }

        // Load chunk c+1 into the other stage (wait for MMA c-1 to release it).
        if (c + 1 < 8) {
            const int s2 = (c + 1) & 1;
            if (c >= 1) {
                MBARRIER_WAIT_PARITY(sb + (s2 ? SMEM_MBAR1 : SMEM_MBAR0), ph[s2] & 1);
                ph[s2]++;
            }
            load_chunk(rowA, rowB, c + 1, sb, s2, tid);
        }
    }

    // Wait for final chunk's MMAs (chunk 7 committed on mbar1; commit covers
    // all previously issued tcgen05.mma from this thread).
    MBARRIER_WAIT_PARITY(sb + SMEM_MBAR1, ph[1] & 1);
    TCGEN05_FENCE_AFTER();

    // Epilogue: each warp owns its 32-row TMEM subpartition; TN=256 cols.
    // Output stores are streaming (__stwt) so the fp16 operand set stays
    // resident in L2 instead of being thrashed by the 256MB output stream.
    const int m = rowA + wid * 32 + lid;
    const float xs = g_xsq[m];
    float* orow = out + (size_t)m * MROWS + rowB;

    #pragma unroll
    for (int nb = 0; nb < TN / 32; ++nb) {
        uint32_t r[32];
        TCGEN05_LD_32X32B_X32(r, tmem + nb * 32);
        TCGEN05_WAIT_LD();
        #pragma unroll
        for (int j = 0; j < 32; j += 4) {
            float4 o;
            float d0 = xs + g_ysq[rowB + nb * 32 + j + 0] - 2.f * __uint_as_float(r[j + 0]);
            float d1 = xs + g_ysq[rowB + nb * 32 + j + 1] - 2.f * __uint_as_float(r[j + 1]);
            float d2 = xs + g_ysq[rowB + nb * 32 + j + 2] - 2.f * __uint_as_float(r[j + 2]);
            float d3 = xs + g_ysq[rowB + nb * 32 + j + 3] - 2.f * __uint_as_float(r[j + 3]);
            o.x = __expf(-GAMMA * fmaxf(d0, 0.f));
            o.y = __expf(-GAMMA * fmaxf(d1, 0.f));
            o.z = __expf(-GAMMA * fmaxf(d2, 0.f));
            o.w = __expf(-GAMMA * fmaxf(d3, 0.f));
            __stwt(reinterpret_cast<float4*>(orow + nb * 32 + j), o);
        }
    }
    TCGEN05_FENCE_BEFORE();

    __syncthreads();
    if (tid == 0) {
        MBARRIER_INVAL(sb + SMEM_MBAR0);
        MBARRIER_INVAL(sb + SMEM_MBAR1);
    }
    __syncthreads();
    if (wid == 0) TCGEN05_DEALLOC(tmem, 256);
}

#else  // !USE_TCGEN05
// ============================================================================
// SIMT fp32 fallback (family / non-'a' passes): same launch geometry,
// tile = 128 x 256 handled as two 128x128 halves.
// ============================================================================
__global__ void __launch_bounds__(128, 2) rbf_gemm_kernel(const float* __restrict__ x,
                                                          const float* __restrict__ y,
                                                          float* __restrict__ out) {
    extern __shared__ __align__(1024) char smem[];
    float* As = reinterpret_cast<float*>(smem);            // [16][128]
    float* Bs = As + 16 * 128;                             // [16][128]

    const int tid = threadIdx.x;
    const int tx = tid & 15;
    const int ty = tid >> 4;
    const int rowA = blockIdx.y * TM;

    for (int half = 0; half < 2; ++half) {
        const int rowB = blockIdx.x * TN + half * 128;

        float acc[16][8];
        #pragma unroll
        for (int i = 0; i < 16; ++i)
            #pragma unroll
            for (int j = 0; j < 8; ++j) acc[i][j] = 0.f;

        for (int k0 = 0; k0 < DDIM; k0 += 16) {
            #pragma unroll
            for (int it = 0; it < 16; ++it) {
                const int idx = it * 128 + tid;
                const int r  = idx >> 4;
                const int kk = idx & 15;
                As[kk * 128 + r] = x[(size_t)(rowA + r) * DDIM + k0 + kk];
                Bs[kk * 128 + r] = y[(size_t)(rowB + r) * DDIM + k0 + kk];
            }
            __syncthreads();
            #pragma unroll
            for (int kk = 0; kk < 16; ++kk) {
                float a[16], b[8];
                #pragma unroll
                for (int i = 0; i < 16; ++i) a[i] = As[kk * 128 + ty * 16 + i];
                #pragma unroll
                for (int j = 0; j < 8; ++j)  b[j] = Bs[kk * 128 + tx * 8 + j];
                #pragma unroll
                for (int i = 0; i < 16; ++i)
                    #pragma unroll
                    for (int j = 0; j < 8; ++j) acc[i][j] += a[i] * b[j];
            }
            __syncthreads();
        }

        #pragma unroll
        for (int i = 0; i < 16; ++i) {
            const int m = rowA + ty * 16 + i;
            const float xs = g_xsq[m];
            #pragma unroll
            for (int j = 0; j < 8; ++j) {
                const int cc = rowB + tx * 8 + j;
                float d = xs + g_ysq[cc] - 2.f * acc[i][j];
                out[(size_t)m * MROWS + cc] = __expf(-GAMMA * fmaxf(d, 0.f));
            }
        }
        __syncthreads();
    }
}
#endif // USE_TCGEN05

// ----------------------------------------------------------------------------
// Launch
// ----------------------------------------------------------------------------
extern "C" void kernel_launch(void* const* d_in, const int* in_sizes, int n_in,
                              void* d_out, int out_size) {
    const float* x = (const float*)d_in[0];
    const float* y = (const float*)d_in[1];
    float* out = (float*)d_out;

    prep_kernel<<<NROWS / 8, 256>>>(x, 0);
    prep_kernel<<<MROWS / 8, 256>>>(y, 1);

    cudaFuncSetAttribute(rbf_gemm_kernel, cudaFuncAttributeMaxDynamicSharedMemorySize,
                         SMEM_TOTAL);
    dim3 grid(MROWS / TN, NROWS / TM);
    rbf_gemm_kernel<<<grid, 128, SMEM_TOTAL>>>(x, y, out);
}

// round 5
// speedup vs baseline: 2.2584x; 1.0821x over previous
#include <cuda_runtime.h>
#include <cuda_fp16.h>
#include <cuda.h>
#include <cstdint>

// ----------------------------------------------------------------------------
// Problem constants
// ----------------------------------------------------------------------------
#define NROWS 8192   // x rows (output rows)
#define MROWS 8192   // y rows (output cols)
#define DDIM  512
#define GAMMA 0.002f

// Tile geometry: CTA computes TM x TN outputs.
#define TM 128
#define TN 256

// tcgen05 is arch-specific (sm_103a). The harness build includes a family
// (plain sm_103) PTX pass where tcgen05 is illegal, so gate on the
// arch-specific feature macros and provide a SIMT fallback for other passes.
#if !defined(__CUDA_ARCH__)
#  define USE_TCGEN05 1
#elif defined(__CUDA_ARCH_FEAT_SM103_ALL) || defined(__CUDA_ARCH_FEAT_SM100_ALL)
#  define USE_TCGEN05 1
#elif defined(__CUDA_ARCH_SPECIFIC__)
#  define USE_TCGEN05 1
#else
#  define USE_TCGEN05 0
#endif

// ----------------------------------------------------------------------------
// Scratch (device globals — no allocation allowed)
// ----------------------------------------------------------------------------
__device__ __half g_xh[NROWS * DDIM];
__device__ __half g_yh[MROWS * DDIM];
__device__ float  g_xsq[NROWS];
__device__ float  g_ysq[MROWS];

// ----------------------------------------------------------------------------
// Prep: fp32 -> fp16 + row |v|^2 (fp32 exact). One launch covers x then y.
// ----------------------------------------------------------------------------
__global__ void __launch_bounds__(256) prep_kernel(const float* __restrict__ x,
                                                   const float* __restrict__ y) {
    const int xblocks = NROWS / 8;
    const int which = (blockIdx.x >= xblocks) ? 1 : 0;
    const int blk   = which ? (blockIdx.x - xblocks) : blockIdx.x;
    const float* in = which ? y : x;
    __half* h  = which ? g_yh : g_xh;
    float* sq  = which ? g_ysq : g_xsq;

    const int warp = threadIdx.x >> 5;
    const int lane = threadIdx.x & 31;
    const int row  = blk * 8 + warp;
    const float* src = in + (size_t)row * DDIM;

    float s = 0.f;
    #pragma unroll
    for (int it = 0; it < 4; ++it) {
        const int col = it * 128 + lane * 4;
        const float4 v = *reinterpret_cast<const float4*>(src + col);
        s += v.x * v.x + v.y * v.y + v.z * v.z + v.w * v.w;

        __half2 p0 = __floats2half2_rn(v.x, v.y);
        __half2 p1 = __floats2half2_rn(v.z, v.w);
        uint2 hv = make_uint2(*reinterpret_cast<uint32_t*>(&p0),
                              *reinterpret_cast<uint32_t*>(&p1));
        *reinterpret_cast<uint2*>(h + (size_t)row * DDIM + col) = hv;
    }
    #pragma unroll
    for (int o = 16; o; o >>= 1) s += __shfl_xor_sync(0xffffffff, s, o);
    if (lane == 0) sq[row] = s;
}

// ----------------------------------------------------------------------------
// SMEM layout:
//   header 1024B: [0] tmem ptr, [8] full0, [16] full1, [24] done0, [32] done1
//   2 stages x (A 16K | B 32K) = 2 x 48K   -> total 99328 bytes (2 CTAs/SM)
// ----------------------------------------------------------------------------
#define A_TILE_BYTES  (TM * 128)              // 16384
#define B_TILE_BYTES  (TN * 128)              // 32768
#define STAGE_BYTES   (A_TILE_BYTES + B_TILE_BYTES)          // 49152
#define SMEM_FULL0    8
#define SMEM_FULL1    16
#define SMEM_DONE0    24
#define SMEM_DONE1    32
#define SMEM_TILES    1024
#define SMEM_TOTAL    (SMEM_TILES + 2 * STAGE_BYTES)         // 99328

#if USE_TCGEN05
// ============================================================================
// tcgen05 + TMA implementation (sm_103a passes only)
// ============================================================================
__device__ __forceinline__ uint32_t smem_u32(const void* p) {
    uint32_t a;
    asm("{ .reg .u64 t; cvta.to.shared.u64 t, %1; cvt.u32.u64 %0, t; }" : "=r"(a) : "l"(p));
    return a;
}

#define TCGEN05_ALLOC(smem_addr, ncols) \
    asm volatile("tcgen05.alloc.cta_group::1.sync.aligned.shared::cta.b32 [%0], %1;" \
                 :: "r"((uint32_t)(smem_addr)), "r"((uint32_t)(ncols)) : "memory")
#define TCGEN05_DEALLOC(tmem, ncols) \
    asm volatile("tcgen05.dealloc.cta_group::1.sync.aligned.b32 %0, %1;" \
                 :: "r"(tmem), "r"((uint32_t)(ncols)))
#define TCGEN05_RELINQ() \
    asm volatile("tcgen05.relinquish_alloc_permit.cta_group::1.sync.aligned;")
#define TCGEN05_COMMIT(mbar) \
    asm volatile("tcgen05.commit.cta_group::1.mbarrier::arrive::one.shared::cluster.b64 [%0];" \
                 :: "r"((uint32_t)(mbar)) : "memory")
#define TCGEN05_WAIT_LD() asm volatile("tcgen05.wait::ld.sync.aligned;" ::: "memory")
#define TCGEN05_FENCE_AFTER()  asm volatile("tcgen05.fence::after_thread_sync;" ::: "memory")
#define TCGEN05_FENCE_BEFORE() asm volatile("tcgen05.fence::before_thread_sync;" ::: "memory")

#define MBARRIER_INIT(mbar, cnt) \
    asm volatile("mbarrier.init.shared.b64 [%0], %1;" \
                 :: "r"((uint32_t)(mbar)), "r"((uint32_t)(cnt)) : "memory")
#define MBARRIER_INVAL(mbar) \
    asm volatile("mbarrier.inval.shared.b64 [%0];" :: "r"((uint32_t)(mbar)) : "memory")
#define MBARRIER_EXPECT_TX(mbar, bytes) \
    asm volatile("mbarrier.arrive.expect_tx.shared.b64 _, [%0], %1;" \
                 :: "r"((uint32_t)(mbar)), "r"((uint32_t)(bytes)) : "memory")

#define MBARRIER_WAIT_PARITY(mbar, parity) do {                                         \
    uint32_t _m = (uint32_t)(mbar);                                                     \
    uint32_t _p = (uint32_t)(parity);                                                   \
    uint32_t _done;                                                                     \
    asm volatile("{\n\t.reg .pred p;\n\t"                                               \
                 "mbarrier.try_wait.parity.acquire.cta.shared::cta.b64 p, [%1], %2;\n\t"\
                 "selp.b32 %0, 1, 0, p;\n\t}"                                           \
                 : "=r"(_done) : "r"(_m), "r"(_p) : "memory");                          \
    if (!_done) {                                                                       \
        asm volatile("{\n\t.reg .pred P1;\n\t"                                          \
            "WAIT_LOOP_%=:\n\t"                                                         \
            "mbarrier.try_wait.parity.acquire.cta.shared::cta.b64 P1, [%0], %1, 0x989680;\n\t" \
            "@P1 bra.uni WAIT_DONE_%=;\n\t"                                             \
            "bra.uni WAIT_LOOP_%=;\n\t"                                                 \
            "WAIT_DONE_%=:\n\t}"                                                        \
            :: "r"(_m), "r"(_p) : "memory");                                            \
    }                                                                                   \
} while (0)

#define TCGEN05_LD_32X32B_X32(r, tmem_addr) \
    asm volatile( \
        "tcgen05.ld.sync.aligned.32x32b.x32.b32 " \
        "{%0, %1, %2, %3, %4, %5, %6, %7, " \
        " %8, %9, %10, %11, %12, %13, %14, %15, " \
        " %16, %17, %18, %19, %20, %21, %22, %23, " \
        " %24, %25, %26, %27, %28, %29, %30, %31}, [%32];" \
        : "=r"((r)[0]),  "=r"((r)[1]),  "=r"((r)[2]),  "=r"((r)[3]), \
          "=r"((r)[4]),  "=r"((r)[5]),  "=r"((r)[6]),  "=r"((r)[7]), \
          "=r"((r)[8]),  "=r"((r)[9]),  "=r"((r)[10]), "=r"((r)[11]), \
          "=r"((r)[12]), "=r"((r)[13]), "=r"((r)[14]), "=r"((r)[15]), \
          "=r"((r)[16]), "=r"((r)[17]), "=r"((r)[18]), "=r"((r)[19]), \
          "=r"((r)[20]), "=r"((r)[21]), "=r"((r)[22]), "=r"((r)[23]), \
          "=r"((r)[24]), "=r"((r)[25]), "=r"((r)[26]), "=r"((r)[27]), \
          "=r"((r)[28]), "=r"((r)[29]), "=r"((r)[30]), "=r"((r)[31]) \
        : "r"(tmem_addr))

__device__ __forceinline__ void tma_load_2d(uint32_t sdst, const CUtensorMap* tm,
                                            int c0, int c1, uint32_t mbar) {
    asm volatile(
        "cp.async.bulk.tensor.2d.shared::cta.global.tile.mbarrier::complete_tx::bytes "
        "[%0], [%1, {%2, %3}], [%4];"
        :: "r"(sdst), "l"(tm), "r"(c0), "r"(c1), "r"(mbar) : "memory");
}

__device__ __forceinline__ void mma_f16_ss(uint32_t d_tmem, uint64_t a_desc,
                                           uint64_t b_desc, uint32_t idesc,
                                           uint32_t enable) {
    asm volatile(
        "{\n\t.reg .pred p;\n\tsetp.ne.u32 p, %4, 0;\n\t"
        "tcgen05.mma.cta_group::1.kind::f16 [%0], %1, %2, %3, {%5, %5, %5, %5}, p;\n\t}"
        :: "r"(d_tmem), "l"(a_desc), "l"(b_desc), "r"(idesc), "r"(enable), "r"(0u)
        : "memory");
}

// SMEM descriptor: SW128, version=1(Blackwell), SBO=64, LBO=1 (K-major 128B rows)
static __device__ __forceinline__ uint64_t make_desc(uint32_t smem_addr) {
    constexpr uint64_t BASE =
        (uint64_t(2) << 61) | (uint64_t(1) << 46) | (uint64_t(64) << 32) | (uint64_t(1) << 16);
    return BASE | ((uint64_t)(smem_addr >> 4) & 0x3FFF);
}

// idesc for kind::f16, fp16 inputs (atype=btype=0), fp32 accum (dtype=1):
#define MMA_IDESC ((1u << 4) | (((unsigned)TN / 8) << 17) | (((unsigned)TM / 16) << 24))

__global__ void __launch_bounds__(128, 2)
rbf_gemm_kernel(const __grid_constant__ CUtensorMap tmA,
                const __grid_constant__ CUtensorMap tmB,
                const float* __restrict__ x, const float* __restrict__ y,
                float* __restrict__ out) {
    extern __shared__ __align__(1024) char smem[];
    const uint32_t sb  = smem_u32(smem);
    const int tid = threadIdx.x;
    const int wid = tid >> 5;
    const int lid = tid & 31;

    if (wid == 0) {
        TCGEN05_ALLOC(sb, 256);
        TCGEN05_RELINQ();
    }
    __syncthreads();
    uint32_t tmem;
    asm volatile("ld.shared.b32 %0, [%1];" : "=r"(tmem) : "r"(sb));

    if (tid == 0) {
        MBARRIER_INIT(sb + SMEM_FULL0, 1);
        MBARRIER_INIT(sb + SMEM_FULL1, 1);
        MBARRIER_INIT(sb + SMEM_DONE0, 1);
        MBARRIER_INIT(sb + SMEM_DONE1, 1);
    }
    __syncthreads();

    const int rowA = blockIdx.y * TM;
    const int rowB = blockIdx.x * TN;

    // ------------------------------------------------------------------
    // Mainloop: entirely single-thread. TMA producer + MMA consumer with
    // per-stage full (tx) and done (mma-commit) barriers. No CTA syncs.
    // ------------------------------------------------------------------
    if (tid == 0) {
        const uint32_t full[2] = {sb + SMEM_FULL0, sb + SMEM_FULL1};
        const uint32_t done[2] = {sb + SMEM_DONE0, sb + SMEM_DONE1};
        const uint32_t stage[2] = {sb + SMEM_TILES, sb + SMEM_TILES + STAGE_BYTES};

        // Prologue: chunks 0,1 into stages 0,1.
        #pragma unroll
        for (int s = 0; s < 2; ++s) {
            MBARRIER_EXPECT_TX(full[s], STAGE_BYTES);
            tma_load_2d(stage[s], &tmA, s * 64, rowA, full[s]);
            tma_load_2d(stage[s] + A_TILE_BYTES, &tmB, s * 64, rowB, full[s]);
        }

        int fp[2] = {0, 0};   // full-barrier wait parities
        int dp[2] = {0, 0};   // done-barrier wait parities

        #pragma unroll
        for (int c = 0; c < 8; ++c) {
            const int s = c & 1;
            MBARRIER_WAIT_PARITY(full[s], fp[s] & 1);
            fp[s]++;

            const uint64_t dA = make_desc(stage[s]);
            const uint64_t dB = make_desc(stage[s] + A_TILE_BYTES);
            #pragma unroll
            for (int k = 0; k < 4; ++k) {          // 4 x K=16 per 64-chunk
                mma_f16_ss(tmem, dA + k * 2, dB + k * 2, MMA_IDESC,
                           (c == 0 && k == 0) ? 0u : 1u);
            }
            TCGEN05_COMMIT(done[s]);

            if (c + 2 < 8) {
                MBARRIER_WAIT_PARITY(done[s], dp[s] & 1);
                dp[s]++;
                MBARRIER_EXPECT_TX(full[s], STAGE_BYTES);
                tma_load_2d(stage[s], &tmA, (c + 2) * 64, rowA, full[s]);
                tma_load_2d(stage[s] + A_TILE_BYTES, &tmB, (c + 2) * 64, rowB, full[s]);
            }
        }
        // Final: chunk 7's commit (done[1], 4th arrival) implies ALL prior
        // MMAs from this thread are complete.
        MBARRIER_WAIT_PARITY(done[1], dp[1] & 1);
    }

    __syncthreads();
    TCGEN05_FENCE_AFTER();

    // ------------------------------------------------------------------
    // Epilogue: each warp owns its 32-row TMEM subpartition; TN=256 cols.
    // __stwt keeps the fp16 operand set L2-resident against the 256MB
    // output stream.
    // ------------------------------------------------------------------
    const int m = rowA + wid * 32 + lid;
    const float xs = g_xsq[m];
    float* orow = out + (size_t)m * MROWS + rowB;

    #pragma unroll
    for (int nb = 0; nb < TN / 32; ++nb) {
        uint32_t r[32];
        TCGEN05_LD_32X32B_X32(r, tmem + nb * 32);
        TCGEN05_WAIT_LD();
        #pragma unroll
        for (int j = 0; j < 32; j += 4) {
            float4 o;
            float d0 = xs + g_ysq[rowB + nb * 32 + j + 0] - 2.f * __uint_as_float(r[j + 0]);
            float d1 = xs + g_ysq[rowB + nb * 32 + j + 1] - 2.f * __uint_as_float(r[j + 1]);
            float d2 = xs + g_ysq[rowB + nb * 32 + j + 2] - 2.f * __uint_as_float(r[j + 2]);
            float d3 = xs + g_ysq[rowB + nb * 32 + j + 3] - 2.f * __uint_as_float(r[j + 3]);
            o.x = __expf(-GAMMA * fmaxf(d0, 0.f));
            o.y = __expf(-GAMMA * fmaxf(d1, 0.f));
            o.z = __expf(-GAMMA * fmaxf(d2, 0.f));
            o.w = __expf(-GAMMA * fmaxf(d3, 0.f));
            __stwt(reinterpret_cast<float4*>(orow + nb * 32 + j), o);
        }
    }
    TCGEN05_FENCE_BEFORE();

    __syncthreads();
    if (tid == 0) {
        MBARRIER_INVAL(sb + SMEM_FULL0);
        MBARRIER_INVAL(sb + SMEM_FULL1);
        MBARRIER_INVAL(sb + SMEM_DONE0);
        MBARRIER_INVAL(sb + SMEM_DONE1);
    }
    __syncthreads();
    if (wid == 0) TCGEN05_DEALLOC(tmem, 256);
}

#else  // !USE_TCGEN05
// ============================================================================
// SIMT fp32 fallback (family / non-'a' passes): same signature/geometry,
// tile = 128 x 256 handled as two 128x128 halves. Uses x/y directly.
// ============================================================================
__global__ void __launch_bounds__(128, 2)
rbf_gemm_kernel(const __grid_constant__ CUtensorMap tmA,
                const __grid_constant__ CUtensorMap tmB,
                const float* __restrict__ x, const float* __restrict__ y,
                float* __restrict__ out) {
    extern __shared__ __align__(1024) char smem[];
    float* As = reinterpret_cast<float*>(smem);            // [16][128]
    float* Bs = As + 16 * 128;                             // [16][128]

    const int tid = threadIdx.x;
    const int tx = tid & 15;
    const int ty = tid >> 4;
    const int rowA = blockIdx.y * TM;

    for (int half = 0; half < 2; ++half) {
        const int rowB = blockIdx.x * TN + half * 128;

        float acc[16][8];
        #pragma unroll
        for (int i = 0; i < 16; ++i)
            #pragma unroll
            for (int j = 0; j < 8; ++j) acc[i][j] = 0.f;

        for (int k0 = 0; k0 < DDIM; k0 += 16) {
            #pragma unroll
            for (int it = 0; it < 16; ++it) {
                const int idx = it * 128 + tid;
                const int r  = idx >> 4;
                const int kk = idx & 15;
                As[kk * 128 + r] = x[(size_t)(rowA + r) * DDIM + k0 + kk];
                Bs[kk * 128 + r] = y[(size_t)(rowB + r) * DDIM + k0 + kk];
            }
            __syncthreads();
            #pragma unroll
            for (int kk = 0; kk < 16; ++kk) {
                float a[16], b[8];
                #pragma unroll
                for (int i = 0; i < 16; ++i) a[i] = As[kk * 128 + ty * 16 + i];
                #pragma unroll
                for (int j = 0; j < 8; ++j)  b[j] = Bs[kk * 128 + tx * 8 + j];
                #pragma unroll
                for (int i = 0; i < 16; ++i)
                    #pragma unroll
                    for (int j = 0; j < 8; ++j) acc[i][j] += a[i] * b[j];
            }
            __syncthreads();
        }

        #pragma unroll
        for (int i = 0; i < 16; ++i) {
            const int m = rowA + ty * 16 + i;
            const float xs = g_xsq[m];
            #pragma unroll
            for (int j = 0; j < 8; ++j) {
                const int cc = rowB + tx * 8 + j;
                float d = xs + g_ysq[cc] - 2.f * acc[i][j];
                out[(size_t)m * MROWS + cc] = __expf(-GAMMA * fmaxf(d, 0.f));
            }
        }
        __syncthreads();
    }
}
#endif // USE_TCGEN05

// ----------------------------------------------------------------------------
// Host: tensor-map construction via runtime driver-entry-point (no -lcuda).
// ----------------------------------------------------------------------------
typedef CUresult (*PFN_tmapEncode)(
    CUtensorMap*, CUtensorMapDataType, cuuint32_t, void*,
    const cuuint64_t*, const cuuint64_t*, const cuuint32_t*, const cuuint32_t*,
    CUtensorMapInterleave, CUtensorMapSwizzle, CUtensorMapL2promotion,
    CUtensorMapFloatOOBfill);

static PFN_tmapEncode get_tmap_encoder() {
    void* fn = nullptr;
    cudaDriverEntryPointQueryResult st;
#if CUDART_VERSION >= 12050
    cudaGetDriverEntryPointByVersion("cuTensorMapEncodeTiled", &fn, 12000,
                                     cudaEnableDefault, &st);
#else
    cudaGetDriverEntryPoint("cuTensorMapEncodeTiled", &fn, cudaEnableDefault, &st);
#endif
    return (PFN_tmapEncode)fn;
}

static void encode_map(PFN_tmapEncode enc, CUtensorMap* tm, void* base,
                       uint64_t rows, uint32_t box_rows) {
    cuuint64_t gdim[2] = {DDIM, rows};
    cuuint64_t gstr[1] = {DDIM * sizeof(__half)};
    cuuint32_t box[2]  = {64, box_rows};          // 64 fp16 = 128B (SW128 max)
    cuuint32_t estr[2] = {1, 1};
    enc(tm, CU_TENSOR_MAP_DATA_TYPE_FLOAT16, 2, base, gdim, gstr, box, estr,
        CU_TENSOR_MAP_INTERLEAVE_NONE, CU_TENSOR_MAP_SWIZZLE_128B,
        CU_TENSOR_MAP_L2_PROMOTION_L2_128B, CU_TENSOR_MAP_FLOAT_OOB_FILL_NONE);
}

extern "C" void kernel_launch(void* const* d_in, const int* in_sizes, int n_in,
                              void* d_out, int out_size) {
    const float* x = (const float*)d_in[0];
    const float* y = (const float*)d_in[1];
    float* out = (float*)d_out;

    prep_kernel<<<NROWS / 8 + MROWS / 8, 256>>>(x, y);

    void* xh_ptr = nullptr;
    void* yh_ptr = nullptr;
    cudaGetSymbolAddress(&xh_ptr, g_xh);
    cudaGetSymbolAddress(&yh_ptr, g_yh);

    CUtensorMap tmA, tmB;
    PFN_tmapEncode enc = get_tmap_encoder();
    encode_map(enc, &tmA, xh_ptr, NROWS, TM);     // box [64, 128]
    encode_map(enc, &tmB, yh_ptr, MROWS, TN);     // box [64, 256]

    cudaFuncSetAttribute(rbf_gemm_kernel, cudaFuncAttributeMaxDynamicSharedMemorySize,
                         SMEM_TOTAL);
    dim3 grid(MROWS / TN, NROWS / TM);
    rbf_gemm_kernel<<<grid, 128, SMEM_TOTAL>>>(tmA, tmB, x, y, out);
}